// round 1
// baseline (speedup 1.0000x reference)
#include <cuda_runtime.h>

// Torch_SINDy: out[n] = poly(u)·c[0:3] + derivs·c[3:6] + derivs·Cm·poly(u)
// with c = coefficients * base_coeffs (PARAM_INIT_VAL = 1).
// big_u is [N,4] row-major float32 -> one float4 per row, fully coalesced.
// Pure HBM-streaming kernel: 16B in + 4B out per row.

__global__ void sindy_kernel(const float4* __restrict__ big_u,
                             const float* __restrict__ coeff,
                             const float* __restrict__ base,
                             float* __restrict__ out,
                             int n) {
    // Broadcast loads: all threads hit the same 15+15 floats (L1-cached).
    float c[15];
#pragma unroll
    for (int i = 0; i < 15; ++i)
        c[i] = __ldg(&coeff[i]) * __ldg(&base[i]);

    int i = blockIdx.x * blockDim.x + threadIdx.x;
    if (i >= n) return;

    float4 v = big_u[i];
    float u  = v.x;
    float u2 = u * u;
    float u3 = u2 * u;
    float y = v.y, z = v.z, w = v.w;

    // linear terms
    float r = u * c[0] + u2 * c[1] + u3 * c[2]
            + y * c[3] + z * c[4] + w * c[5];

    // bilinear term: derivs[d] * poly[f] * Cm[d][f], Cm[d][f] = c[6+3d+f]
    r += y * (u * c[6]  + u2 * c[7]  + u3 * c[8]);
    r += z * (u * c[9]  + u2 * c[10] + u3 * c[11]);
    r += w * (u * c[12] + u2 * c[13] + u3 * c[14]);

    out[i] = r;
}

extern "C" void kernel_launch(void* const* d_in, const int* in_sizes, int n_in,
                              void* d_out, int out_size) {
    const float4* big_u = (const float4*)d_in[0];   // [N,4] f32
    const float*  coeff = (const float*)d_in[1];    // [15]  f32
    const float*  base  = (const float*)d_in[2];    // [15]  f32
    float* out = (float*)d_out;                     // [N,1] f32

    int n = in_sizes[0] / 4;   // rows
    const int threads = 256;
    int blocks = (n + threads - 1) / threads;
    sindy_kernel<<<blocks, threads>>>(big_u, coeff, base, out, n);
}

// round 2
// speedup vs baseline: 1.4215x; 1.4215x over previous
#include <cuda_runtime.h>

// Torch_SINDy: out[n] = poly(u)·c[0:3] + derivs·c[3:6] + derivs·Cm·poly(u)
// HBM-streaming: 16B in + 4B out per row. R1 showed L1-bound (80.8%) from
// 30 scalar coeff LDGs/thread. Fix: vector coeff loads + 4 rows/thread.

#define ITEMS 4
#define THREADS 256

__global__ void __launch_bounds__(THREADS)
sindy_kernel(const float4* __restrict__ big_u,
             const float*  __restrict__ coeff,
             const float*  __restrict__ base,
             float*        __restrict__ out,
             int n) {
    // Coefficient product c[i] = coeff[i]*base[i], loaded with 3 vec4 + 3 scalar
    // loads per array (12 L1 wavefronts total, broadcast across the warp).
    float c[15];
    {
        const float4* c4 = (const float4*)coeff;
        const float4* b4 = (const float4*)base;
#pragma unroll
        for (int q = 0; q < 3; ++q) {
            float4 cv = __ldg(&c4[q]);
            float4 bv = __ldg(&b4[q]);
            c[q*4+0] = cv.x * bv.x;
            c[q*4+1] = cv.y * bv.y;
            c[q*4+2] = cv.z * bv.z;
            c[q*4+3] = cv.w * bv.w;
        }
#pragma unroll
        for (int q = 12; q < 15; ++q)
            c[q] = __ldg(&coeff[q]) * __ldg(&base[q]);
    }

    int base_i = blockIdx.x * (THREADS * ITEMS) + threadIdx.x;

    // Front-batch all 4 row loads (MLP=4) before computing.
    float4 v[ITEMS];
#pragma unroll
    for (int k = 0; k < ITEMS; ++k) {
        int i = base_i + k * THREADS;
        if (i < n) v[k] = big_u[i];
    }

#pragma unroll
    for (int k = 0; k < ITEMS; ++k) {
        int i = base_i + k * THREADS;
        if (i >= n) continue;
        float u  = v[k].x;
        float u2 = u * u;
        float u3 = u2 * u;
        float y = v[k].y, z = v[k].z, w = v[k].w;

        float r = u * c[0] + u2 * c[1] + u3 * c[2]
                + y * c[3] + z * c[4] + w * c[5];
        r += y * (u * c[6]  + u2 * c[7]  + u3 * c[8]);
        r += z * (u * c[9]  + u2 * c[10] + u3 * c[11]);
        r += w * (u * c[12] + u2 * c[13] + u3 * c[14]);

        out[i] = r;
    }
}

extern "C" void kernel_launch(void* const* d_in, const int* in_sizes, int n_in,
                              void* d_out, int out_size) {
    const float4* big_u = (const float4*)d_in[0];   // [N,4] f32
    const float*  coeff = (const float*)d_in[1];    // [15]  f32
    const float*  base  = (const float*)d_in[2];    // [15]  f32
    float* out = (float*)d_out;                     // [N,1] f32

    int n = in_sizes[0] / 4;   // rows
    int per_block = THREADS * ITEMS;
    int blocks = (n + per_block - 1) / per_block;
    sindy_kernel<<<blocks, THREADS>>>(big_u, coeff, base, out, n);
}

// round 3
// speedup vs baseline: 1.6539x; 1.1635x over previous
#include <cuda_runtime.h>

// Torch_SINDy streaming kernel. R2: DRAM=72%, latency-exposed (occ 50%,
// issue 36%, MLP=4). R3: MLP=8 front-batched loads, streaming cache hints,
// unguarded fast path for the exact-divide grid.

#define ITEMS 8
#define THREADS 256

__device__ __forceinline__ float sindy_row(float4 v, const float* c) {
    float u  = v.x;
    float u2 = u * u;
    float u3 = u2 * u;
    float y = v.y, z = v.z, w = v.w;
    float r = u * c[0] + u2 * c[1] + u3 * c[2]
            + y * c[3] + z * c[4] + w * c[5];
    r += y * (u * c[6]  + u2 * c[7]  + u3 * c[8]);
    r += z * (u * c[9]  + u2 * c[10] + u3 * c[11]);
    r += w * (u * c[12] + u2 * c[13] + u3 * c[14]);
    return r;
}

__device__ __forceinline__ void load_coeffs(const float* __restrict__ coeff,
                                            const float* __restrict__ base,
                                            float* c) {
    const float4* c4 = (const float4*)coeff;
    const float4* b4 = (const float4*)base;
#pragma unroll
    for (int q = 0; q < 3; ++q) {
        float4 cv = __ldg(&c4[q]);
        float4 bv = __ldg(&b4[q]);
        c[q*4+0] = cv.x * bv.x;
        c[q*4+1] = cv.y * bv.y;
        c[q*4+2] = cv.z * bv.z;
        c[q*4+3] = cv.w * bv.w;
    }
#pragma unroll
    for (int q = 12; q < 15; ++q)
        c[q] = __ldg(&coeff[q]) * __ldg(&base[q]);
}

// Fast path: grid exactly covers n, no bounds checks -> 8 unguarded
// front-batched LDG.128 (MLP=8), streaming (evict-first) hints.
__global__ void __launch_bounds__(THREADS)
sindy_kernel_exact(const float4* __restrict__ big_u,
                   const float*  __restrict__ coeff,
                   const float*  __restrict__ base,
                   float*        __restrict__ out) {
    float c[15];
    load_coeffs(coeff, base, c);

    int base_i = blockIdx.x * (THREADS * ITEMS) + threadIdx.x;

    float4 v[ITEMS];
#pragma unroll
    for (int k = 0; k < ITEMS; ++k)
        v[k] = __ldcs(&big_u[base_i + k * THREADS]);

#pragma unroll
    for (int k = 0; k < ITEMS; ++k)
        __stcs(&out[base_i + k * THREADS], sindy_row(v[k], c));
}

// Guarded fallback for arbitrary n.
__global__ void __launch_bounds__(THREADS)
sindy_kernel_guarded(const float4* __restrict__ big_u,
                     const float*  __restrict__ coeff,
                     const float*  __restrict__ base,
                     float*        __restrict__ out,
                     int n) {
    float c[15];
    load_coeffs(coeff, base, c);

    int base_i = blockIdx.x * (THREADS * ITEMS) + threadIdx.x;

    float4 v[ITEMS];
#pragma unroll
    for (int k = 0; k < ITEMS; ++k) {
        int i = base_i + k * THREADS;
        if (i < n) v[k] = __ldcs(&big_u[i]);
    }
#pragma unroll
    for (int k = 0; k < ITEMS; ++k) {
        int i = base_i + k * THREADS;
        if (i < n) __stcs(&out[i], sindy_row(v[k], c));
    }
}

extern "C" void kernel_launch(void* const* d_in, const int* in_sizes, int n_in,
                              void* d_out, int out_size) {
    const float4* big_u = (const float4*)d_in[0];   // [N,4] f32
    const float*  coeff = (const float*)d_in[1];    // [15]  f32
    const float*  base  = (const float*)d_in[2];    // [15]  f32
    float* out = (float*)d_out;                     // [N,1] f32

    int n = in_sizes[0] / 4;   // rows
    const int per_block = THREADS * ITEMS;
    int blocks = (n + per_block - 1) / per_block;

    if (n % per_block == 0) {
        sindy_kernel_exact<<<blocks, THREADS>>>(big_u, coeff, base, out);
    } else {
        sindy_kernel_guarded<<<blocks, THREADS>>>(big_u, coeff, base, out, n);
    }
}